// round 4
// baseline (speedup 1.0000x reference)
#include <cuda_runtime.h>
#include <stdint.h>

// Instant-NGP hash-grid interpolation encoding.
// B=262144 points, DIM=3, L=16 levels, T=19 (2^19-entry tables), F=2 features.
//
// R2: PRIMES[0]==1 -> even g0 collapses x-corner pairs into aligned float4 loads.
// R4: L1-bypass (__ldcg) for high-footprint levels (l>=5, footprint >= 1MB):
//     their gathers always miss L1; bypassing kills the L1 fill-write work and
//     stops them thrashing the small levels' resident lines.

#define NB   262144
#define NL   16
#define TBITS 19
#define TMASK ((1u << TBITS) - 1u)
#define CG_LEVEL 5   // levels >= this bypass L1

__constant__ float c_res[NL] = {
    16.f, 20.f, 25.f, 32.f, 40.f, 50.f, 64.f, 80.f,
    101.f, 128.f, 161.f, 203.f, 256.f, 322.f, 406.f, 512.f
};

template<bool CG>
__device__ __forceinline__ float2 ld2(const float2* p) {
    return CG ? __ldcg(p) : __ldg(p);
}
template<bool CG>
__device__ __forceinline__ float4 ld4(const float4* p) {
    return CG ? __ldcg(p) : __ldg(p);
}

template<bool CG>
__device__ __forceinline__ float2 gather_interp(
    const float2* __restrict__ tab,
    unsigned g0, const unsigned hy[4],
    float w0a, float w0b, const float wp[4])
{
    float a0 = 0.f, a1 = 0.f;

    if ((g0 & 1u) == 0u) {
        // g0 even: x-corner pair = {idx, idx^1} -> one aligned float4.
        const float4* __restrict__ tab4 = (const float4*)tab;

        unsigned idxA[4];
#pragma unroll
        for (int p = 0; p < 4; p++) idxA[p] = (g0 ^ hy[p]) & TMASK;

        float4 q[4];
#pragma unroll
        for (int p = 0; p < 4; p++) q[p] = ld4<CG>(tab4 + (idxA[p] >> 1));

#pragma unroll
        for (int p = 0; p < 4; p++) {
            const bool hi = (idxA[p] & 1u) != 0u;
            const float vax = hi ? q[p].z : q[p].x;
            const float vay = hi ? q[p].w : q[p].y;
            const float vbx = hi ? q[p].x : q[p].z;
            const float vby = hi ? q[p].y : q[p].w;
            const float wA = w0a * wp[p];
            const float wB = w0b * wp[p];
            a0 += wA * vax + wB * vbx;
            a1 += wA * vay + wB * vby;
        }
    } else {
        // g0 odd: 8 independent float2 gathers.
        const unsigned h0a = g0, h0b = g0 + 1u;

        unsigned idx[8];
#pragma unroll
        for (int p = 0; p < 4; p++) {
            idx[2 * p + 0] = (h0a ^ hy[p]) & TMASK;
            idx[2 * p + 1] = (h0b ^ hy[p]) & TMASK;
        }

        float2 v[8];
#pragma unroll
        for (int i = 0; i < 8; i++) v[i] = ld2<CG>(tab + idx[i]);

#pragma unroll
        for (int p = 0; p < 4; p++) {
            const float wA = w0a * wp[p];
            const float wB = w0b * wp[p];
            a0 += wA * v[2 * p].x + wB * v[2 * p + 1].x;
            a1 += wA * v[2 * p].y + wB * v[2 * p + 1].y;
        }
    }
    return make_float2(a0, a1);
}

__global__ void __launch_bounds__(256, 8)
ngp_interp_kernel(const float* __restrict__ x,
                  const float2* __restrict__ tables,
                  float2* __restrict__ out)
{
    const int tid = blockIdx.x * 256 + threadIdx.x;   // tid = b*16 + l
    const int l = tid & (NL - 1);
    const int b = tid >> 4;

    const float res = c_res[l];

    const float x0 = __ldg(x + b * 3 + 0);
    const float x1 = __ldg(x + b * 3 + 1);
    const float x2 = __ldg(x + b * 3 + 2);

    const float s0 = x0 * res, s1 = x1 * res, s2 = x2 * res;
    const float g0f = floorf(s0), g1f = floorf(s1), g2f = floorf(s2);
    const float f0 = s0 - g0f, f1 = s1 - g1f, f2 = s2 - g2f;

    const unsigned g0 = (unsigned)g0f;
    const unsigned g1 = (unsigned)g1f;
    const unsigned g2 = (unsigned)g2f;

    const unsigned P1 = 2654435761u, P2 = 805459861u;

    const unsigned h1a = g1 * P1, h1b = (g1 + 1u) * P1;
    const unsigned h2a = g2 * P2, h2b = (g2 + 1u) * P2;

    const float2* __restrict__ tab = tables + ((size_t)l << TBITS);

    const float w0a = 1.f - f0, w0b = f0;
    const float w1a = 1.f - f1, w1b = f1;
    const float w2a = 1.f - f2, w2b = f2;

    unsigned hy[4];
    hy[0] = h1a ^ h2a;  hy[1] = h1b ^ h2a;
    hy[2] = h1a ^ h2b;  hy[3] = h1b ^ h2b;

    float wp[4];
    wp[0] = w1a * w2a;  wp[1] = w1b * w2a;
    wp[2] = w1a * w2b;  wp[3] = w1b * w2b;

    float2 r;
    if (l >= CG_LEVEL) {
        r = gather_interp<true >(tab, g0, hy, w0a, w0b, wp);
    } else {
        r = gather_interp<false>(tab, g0, hy, w0a, w0b, wp);
    }

    out[tid] = r;   // out[b,l]: fully coalesced
}

extern "C" void kernel_launch(void* const* d_in, const int* in_sizes, int n_in,
                              void* d_out, int out_size)
{
    const float* x   = (const float*)d_in[0];
    const float* tab = (const float*)d_in[1];
    if (n_in >= 2 && in_sizes[0] > in_sizes[1]) {
        const float* t = x; x = tab; tab = t;
    }

    const int total = NB * NL;
    ngp_interp_kernel<<<total / 256, 256>>>(x, (const float2*)tab, (float2*)d_out);
}

// round 5
// speedup vs baseline: 1.0810x; 1.0810x over previous
#include <cuda_runtime.h>
#include <stdint.h>

// Instant-NGP hash-grid interpolation encoding.
// B=262144 points, DIM=3, L=16 levels, T=19 (2^19-entry tables), F=2 features.
//
// R2: PRIMES[0]==1 -> x-corner pair differs by m = g0^(g0+1) in table index.
//     m=1 (even g0, p=1/2): pair inside one aligned float4 -> 4 loads.
// R5: m=3 (g0%4==1, p=1/4): pair inside one 32B-aligned 4-entry group ->
//     one 256-bit ld.global.v8.f32 (Blackwell) per combo -> 4 loads.
//     m>=7 (p=1/4): 8 independent float2 gathers.
// Avg lane-loads: 5 (vs 6 in R2, 8 in R1). L1tex-wavefront bound kernel.
// R4 (.cg bypass) reverted: regressed, L1tex work is not fill-policy sensitive.

#define NB   262144
#define NL   16
#define TBITS 19
#define TMASK ((1u << TBITS) - 1u)

__constant__ float c_res[NL] = {
    16.f, 20.f, 25.f, 32.f, 40.f, 50.f, 64.f, 80.f,
    101.f, 128.f, 161.f, 203.f, 256.f, 322.f, 406.f, 512.f
};

struct F8 { float v0, v1, v2, v3, v4, v5, v6, v7; };

// 256-bit global load (sm_100+). 32B-aligned address required.
__device__ __forceinline__ F8 ldg256(const float* p) {
    F8 r;
    unsigned long long ga = (unsigned long long)__cvta_generic_to_global((void*)p);
    asm("ld.global.v8.f32 {%0,%1,%2,%3,%4,%5,%6,%7}, [%8];"
        : "=f"(r.v0), "=f"(r.v1), "=f"(r.v2), "=f"(r.v3),
          "=f"(r.v4), "=f"(r.v5), "=f"(r.v6), "=f"(r.v7)
        : "l"(ga));
    return r;
}

// Select entry s (0..3) from 4 values without local-memory indexing.
__device__ __forceinline__ float sel4(unsigned s, float a, float b, float c, float d) {
    const float lo = (s & 1u) ? b : a;
    const float hi = (s & 1u) ? d : c;
    return (s & 2u) ? hi : lo;
}

__global__ void __launch_bounds__(256)
ngp_interp_kernel(const float* __restrict__ x,
                  const float2* __restrict__ tables,
                  float2* __restrict__ out)
{
    const int tid = blockIdx.x * 256 + threadIdx.x;   // tid = b*16 + l
    const int l = tid & (NL - 1);
    const int b = tid >> 4;

    const float res = c_res[l];

    const float x0 = __ldg(x + b * 3 + 0);
    const float x1 = __ldg(x + b * 3 + 1);
    const float x2 = __ldg(x + b * 3 + 2);

    const float s0 = x0 * res, s1 = x1 * res, s2 = x2 * res;
    const float g0f = floorf(s0), g1f = floorf(s1), g2f = floorf(s2);
    const float f0 = s0 - g0f, f1 = s1 - g1f, f2 = s2 - g2f;

    const unsigned g0 = (unsigned)g0f;
    const unsigned g1 = (unsigned)g1f;
    const unsigned g2 = (unsigned)g2f;

    const unsigned P1 = 2654435761u, P2 = 805459861u;

    const unsigned h1a = g1 * P1, h1b = (g1 + 1u) * P1;
    const unsigned h2a = g2 * P2, h2b = (g2 + 1u) * P2;

    const float2* __restrict__ tab = tables + ((size_t)l << TBITS);

    const float w0a = 1.f - f0, w0b = f0;
    const float w1a = 1.f - f1, w1b = f1;
    const float w2a = 1.f - f2, w2b = f2;

    unsigned hy[4];
    hy[0] = h1a ^ h2a;  hy[1] = h1b ^ h2a;
    hy[2] = h1a ^ h2b;  hy[3] = h1b ^ h2b;

    float wp[4];
    wp[0] = w1a * w2a;  wp[1] = w1b * w2a;
    wp[2] = w1a * w2b;  wp[3] = w1b * w2b;

    // m = g0 ^ (g0+1): index delta between the two x-corners.
    const unsigned m = g0 ^ (g0 + 1u);

    float a0 = 0.f, a1 = 0.f;

    if (m == 1u) {
        // Even g0: pair {idx, idx^1} inside one aligned float4.
        const float4* __restrict__ tab4 = (const float4*)tab;

        unsigned idxA[4];
#pragma unroll
        for (int p = 0; p < 4; p++) idxA[p] = (g0 ^ hy[p]) & TMASK;

        float4 q[4];
#pragma unroll
        for (int p = 0; p < 4; p++) q[p] = __ldg(tab4 + (idxA[p] >> 1));

#pragma unroll
        for (int p = 0; p < 4; p++) {
            const bool hi = (idxA[p] & 1u) != 0u;
            const float vax = hi ? q[p].z : q[p].x;
            const float vay = hi ? q[p].w : q[p].y;
            const float vbx = hi ? q[p].x : q[p].z;
            const float vby = hi ? q[p].y : q[p].w;
            const float wA = w0a * wp[p];
            const float wB = w0b * wp[p];
            a0 += wA * vax + wB * vbx;
            a1 += wA * vay + wB * vby;
        }
    } else if (m == 3u) {
        // g0 % 4 == 1: pair {idx, idx^3} inside one 32B-aligned 4-entry group.
        const float* __restrict__ tabf = (const float*)tab;

        unsigned i0[4];
#pragma unroll
        for (int p = 0; p < 4; p++) i0[p] = (g0 ^ hy[p]) & TMASK;

        F8 q[4];
#pragma unroll
        for (int p = 0; p < 4; p++)
            q[p] = ldg256(tabf + ((size_t)(i0[p] >> 2) << 3));

#pragma unroll
        for (int p = 0; p < 4; p++) {
            const unsigned sA = i0[p] & 3u;      // corner g0   (weight w0a)
            const unsigned sB = sA ^ 3u;         // corner g0+1 (weight w0b)
            const float vax = sel4(sA, q[p].v0, q[p].v2, q[p].v4, q[p].v6);
            const float vay = sel4(sA, q[p].v1, q[p].v3, q[p].v5, q[p].v7);
            const float vbx = sel4(sB, q[p].v0, q[p].v2, q[p].v4, q[p].v6);
            const float vby = sel4(sB, q[p].v1, q[p].v3, q[p].v5, q[p].v7);
            const float wA = w0a * wp[p];
            const float wB = w0b * wp[p];
            a0 += wA * vax + wB * vbx;
            a1 += wA * vay + wB * vby;
        }
    } else {
        // m >= 7: corners in unrelated 32B groups -> 8 float2 gathers.
        const unsigned h0a = g0, h0b = g0 + 1u;

        unsigned idx[8];
#pragma unroll
        for (int p = 0; p < 4; p++) {
            idx[2 * p + 0] = (h0a ^ hy[p]) & TMASK;
            idx[2 * p + 1] = (h0b ^ hy[p]) & TMASK;
        }

        float2 v[8];
#pragma unroll
        for (int i = 0; i < 8; i++) v[i] = __ldg(tab + idx[i]);

#pragma unroll
        for (int p = 0; p < 4; p++) {
            const float wA = w0a * wp[p];
            const float wB = w0b * wp[p];
            a0 += wA * v[2 * p].x + wB * v[2 * p + 1].x;
            a1 += wA * v[2 * p].y + wB * v[2 * p + 1].y;
        }
    }

    out[tid] = make_float2(a0, a1);   // out[b,l]: fully coalesced
}

extern "C" void kernel_launch(void* const* d_in, const int* in_sizes, int n_in,
                              void* d_out, int out_size)
{
    const float* x   = (const float*)d_in[0];
    const float* tab = (const float*)d_in[1];
    if (n_in >= 2 && in_sizes[0] > in_sizes[1]) {
        const float* t = x; x = tab; tab = t;
    }

    const int total = NB * NL;
    ngp_interp_kernel<<<total / 256, 256>>>(x, (const float2*)tab, (float2*)d_out);
}